// round 2
// baseline (speedup 1.0000x reference)
#include <cuda_runtime.h>
#include <math.h>

#define BB 8
#define CC 4
#define HH 192
#define WW 192
#define HW (HH*WW)
#define NP 24          // (batch, class) pairs: 8 * 3
#define NM 48          // masks: pair*2 + {0:pred surface, 1:gt surface}
#define NBINS 73728    // 288*256 fine bins over integer squared distances
#define NCOARSE 288
#define SENT_KEY 73727 // sentinel bin for f == 1e9 (empty source surface)

__device__ unsigned char d_pred[BB*HW];
__device__ unsigned char d_surf[NM*HW];
__device__ float         d_g[NM*HW];
__device__ __align__(16) int d_hist[NM*NBINS];
__device__ __align__(16) int d_coarse[NM*NCOARSE];
__device__ float         d_res[NM*2];   // [m][0]=p95, [m][1]=p100

// ---------------------------------------------------------------- clear
__global__ void clear_kernel() {
    int idx = blockIdx.x*blockDim.x + threadIdx.x;
    int stride = gridDim.x*blockDim.x;
    int4 z = make_int4(0,0,0,0);
    int4* h4 = (int4*)d_hist;
    for (int k = idx; k < NM*NBINS/4; k += stride) h4[k] = z;
    int4* c4 = (int4*)d_coarse;
    for (int k = idx; k < NM*NCOARSE/4; k += stride) c4[k] = z;
}

// ---------------------------------------------------------------- argmax (softmax is monotone; first-max tie rule)
__global__ void argmax_kernel(const float* __restrict__ logits) {
    int pix = blockIdx.x*blockDim.x + threadIdx.x;
    if (pix >= BB*HW) return;
    int b = pix / HW;
    int p = pix - b*HW;
    const float* base = logits + (size_t)b*CC*HW + p;
    float best = base[0];
    int bi = 0;
    #pragma unroll
    for (int c = 1; c < CC; c++) {
        float v = base[(size_t)c*HW];
        if (v > best) { best = v; bi = c; }
    }
    d_pred[pix] = (unsigned char)bi;
}

// ---------------------------------------------------------------- surfaces (4-neighbor, image border = background)
// NOTE: target is int32 (JAX x64-disabled downcasts the reference's int64).
__global__ void surface_kernel(const int* __restrict__ target) {
    int idx = blockIdx.x*blockDim.x + threadIdx.x;
    if (idx >= NP*HW) return;
    int pair = idx / HW;
    int pix  = idx - pair*HW;
    int b = pair / 3;
    int c = pair - b*3 + 1;
    int i = pix / WW;
    int j = pix - i*WW;
    {
        const unsigned char* P = d_pred + b*HW;
        bool fg = (P[pix] == c);
        bool s = false;
        if (fg) {
            bool up = (i > 0)     && (P[pix-WW] == c);
            bool dn = (i < HH-1)  && (P[pix+WW] == c);
            bool lf = (j > 0)     && (P[pix-1]  == c);
            bool rt = (j < WW-1)  && (P[pix+1]  == c);
            s = !(up && dn && lf && rt);
        }
        d_surf[(pair*2+0)*HW + pix] = s ? 1 : 0;
    }
    {
        const int* T = target + (size_t)b*HW;
        bool fg = (T[pix] == c);
        bool s = false;
        if (fg) {
            bool up = (i > 0)     && (T[pix-WW] == c);
            bool dn = (i < HH-1)  && (T[pix+WW] == c);
            bool lf = (j > 0)     && (T[pix-1]  == c);
            bool rt = (j < WW-1)  && (T[pix+1]  == c);
            s = !(up && dn && lf && rt);
        }
        d_surf[(pair*2+1)*HW + pix] = s ? 1 : 0;
    }
}

// ---------------------------------------------------------------- pass 1: per-column squared distance to nearest surface row
// Exact: g[i,j] = (min_{i' in surf(col j)} |i-i'|)^2, or 1e9 if column empty.
__global__ void colpass_kernel() {
    int m = blockIdx.x;      // 48 masks
    int j = threadIdx.x;     // 192 columns
    const unsigned char* s = d_surf + m*HW;
    float* g = d_g + m*HW;
    int cnt = 255;
    for (int i = 0; i < HH; i++) {
        cnt = s[i*WW+j] ? 0 : min(cnt+1, 255);
        g[i*WW+j] = (float)cnt;            // temp: distance downward
    }
    cnt = 255;
    for (int i = HH-1; i >= 0; i--) {
        cnt = s[i*WW+j] ? 0 : min(cnt+1, 255);
        int d = min(cnt, (int)g[i*WW+j]);
        g[i*WW+j] = (d >= HH) ? 1e9f : (float)(d*d);
    }
}

// ---------------------------------------------------------------- pass 2: min-plus over columns, fused with histogram scatter
// f[i,j] = min_jp fma((j-jp),(j-jp), g[i,jp])  (exact integers, or 1e9 when mask empty)
// Sample at the opposite surface (m^1) and scatter integer key into per-mask histograms.
__global__ void rowpass_kernel() {
    int m = blockIdx.x / HH;
    int i = blockIdx.x - m*HH;
    int j = threadIdx.x;
    __shared__ float gs[WW];
    gs[j] = d_g[m*HW + i*WW + j];
    __syncthreads();
    float jj = (float)j;
    float v = 3.0e9f;
    #pragma unroll 8
    for (int jp = 0; jp < WW; jp++) {
        float dd = jj - (float)jp;
        v = fminf(v, fmaf(dd, dd, gs[jp]));
    }
    if (d_surf[(m ^ 1)*HW + i*WW + j]) {
        int key = (v > 73000.0f) ? SENT_KEY : (int)v;   // v is an exact integer or 1e9
        atomicAdd(&d_coarse[m*NCOARSE + (key >> 8)], 1);
        atomicAdd(&d_hist[m*NBINS + key], 1);
    }
}

// ---------------------------------------------------------------- per-mask selection: p95 rank = ceil(0.95f*n), p100 rank = n
__global__ void select_kernel() {
    int m = blockIdx.x;
    __shared__ int cs[NCOARSE];
    __shared__ int fs[2][256];
    __shared__ int cbsel[2];
    __shared__ int rrem[2];
    __shared__ int nsh;
    int t = threadIdx.x;
    if (t < NCOARSE) cs[t] = d_coarse[m*NCOARSE + t];
    __syncthreads();
    if (t == 0) {
        int n = 0;
        for (int k = 0; k < NCOARSE; k++) n += cs[k];
        nsh = n;
        if (n > 0) {
            int r95 = (int)ceilf(0.95f * (float)n);   // matches jnp: f32 0.95 * f32 n, ceil
            if (r95 < 1) r95 = 1;
            if (r95 > n) r95 = n;
            int ranks[2] = { r95, n };
            for (int q = 0; q < 2; q++) {
                int r = ranks[q];
                int cum = 0, cb = NCOARSE - 1;
                for (int k = 0; k < NCOARSE; k++) {
                    if (cum + cs[k] >= r) { cb = k; break; }
                    cum += cs[k];
                }
                cbsel[q] = cb;
                rrem[q]  = r - cum;
            }
        }
    }
    __syncthreads();
    if (nsh == 0) {
        if (t < 2) d_res[m*2 + t] = INFINITY;
        return;
    }
    for (int q = 0; q < 2; q++)
        if (t < 256) fs[q][t] = d_hist[m*NBINS + cbsel[q]*256 + t];
    __syncthreads();
    if (t == 0) {
        for (int q = 0; q < 2; q++) {
            int cum = 0;
            int key = cbsel[q]*256;
            for (int k = 0; k < 256; k++) {
                cum += fs[q][k];
                if (cum >= rrem[q]) { key += k; break; }
            }
            float val = (key == SENT_KEY) ? sqrtf(1e9f) : sqrtf((float)key);
            d_res[m*2 + q] = val;  // q=0: p95, q=1: p100
        }
    }
}

// ---------------------------------------------------------------- combine: max over directions, mean over 24 pairs
__global__ void final_kernel(float* __restrict__ out) {
    if (threadIdx.x == 0) {
        float s100 = 0.0f, s95 = 0.0f;
        #pragma unroll
        for (int p = 0; p < NP; p++) {
            s95  += fmaxf(d_res[(2*p)*2 + 0], d_res[(2*p+1)*2 + 0]);
            s100 += fmaxf(d_res[(2*p)*2 + 1], d_res[(2*p+1)*2 + 1]);
        }
        out[0] = s100 / (float)NP;
        out[1] = s95  / (float)NP;
    }
}

extern "C" void kernel_launch(void* const* d_in, const int* in_sizes, int n_in,
                              void* d_out, int out_size) {
    const float* logits = (const float*)d_in[0];
    const int*   target = (const int*)d_in[1];
    float* out = (float*)d_out;

    clear_kernel  <<<2048, 256>>>();
    argmax_kernel <<<(BB*HW + 255)/256, 256>>>(logits);
    surface_kernel<<<(NP*HW + 255)/256, 256>>>(target);
    colpass_kernel<<<NM, WW>>>();
    rowpass_kernel<<<NM*HH, WW>>>();
    select_kernel <<<NM, NCOARSE>>>();
    final_kernel  <<<1, 32>>>(out);
}

// round 3
// speedup vs baseline: 1.8914x; 1.8914x over previous
#include <cuda_runtime.h>
#include <math.h>

#define BB 8
#define CC 4
#define HH 192
#define WW 192
#define HW (HH*WW)
#define NP 24          // (batch, class) pairs: 8 * 3
#define NM 48          // masks: pair*2 + {0:pred surface, 1:gt surface}
#define NBINS 73728    // 288*256 fine bins over integer squared distances
#define NCOARSE 288
#define SENT_KEY 73727 // sentinel bin for f == 1e9 (empty source surface)

__device__ unsigned char  d_pred[BB*HW];
__device__ unsigned char  d_surf[NM*HW];
__device__ unsigned char  d_cols[NM*HW];     // per-row compacted sample columns
__device__ short          d_cnt[NM*HH];      // samples per row
__device__ unsigned short d_g16[NM*HW];      // column-pass squared distance (65535 = inf)
__device__ __align__(16) int d_hist[NM*NBINS];
__device__ __align__(16) int d_coarse[NM*NCOARSE];
__device__ float          d_res[NM*2];       // [m][0]=p95, [m][1]=p100

// ---------------------------------------------------------------- clear
__global__ void clear_kernel() {
    int idx = blockIdx.x*blockDim.x + threadIdx.x;
    int stride = gridDim.x*blockDim.x;
    int4 z = make_int4(0,0,0,0);
    int4* h4 = (int4*)d_hist;
    for (int k = idx; k < NM*NBINS/4; k += stride) h4[k] = z;
    int4* c4 = (int4*)d_coarse;
    for (int k = idx; k < NM*NCOARSE/4; k += stride) c4[k] = z;
}

// ---------------------------------------------------------------- argmax (softmax is monotone; first-max tie rule)
__global__ void argmax_kernel(const float* __restrict__ logits) {
    int pix = blockIdx.x*blockDim.x + threadIdx.x;
    if (pix >= BB*HW) return;
    int b = pix / HW;
    int p = pix - b*HW;
    const float* base = logits + (size_t)b*CC*HW + p;
    float best = base[0];
    int bi = 0;
    #pragma unroll
    for (int c = 1; c < CC; c++) {
        float v = base[(size_t)c*HW];
        if (v > best) { best = v; bi = c; }
    }
    d_pred[pix] = (unsigned char)bi;
}

// ---------------------------------------------------------------- surfaces (4-neighbor, image border = background)
// target is int32 (JAX x64-disabled downcasts the reference's int64).
__global__ void surface_kernel(const int* __restrict__ target) {
    int idx = blockIdx.x*blockDim.x + threadIdx.x;
    if (idx >= NP*HW) return;
    int pair = idx / HW;
    int pix  = idx - pair*HW;
    int b = pair / 3;
    int c = pair - b*3 + 1;
    int i = pix / WW;
    int j = pix - i*WW;
    {
        const unsigned char* P = d_pred + b*HW;
        bool fg = (P[pix] == c);
        bool s = false;
        if (fg) {
            bool up = (i > 0)     && (P[pix-WW] == c);
            bool dn = (i < HH-1)  && (P[pix+WW] == c);
            bool lf = (j > 0)     && (P[pix-1]  == c);
            bool rt = (j < WW-1)  && (P[pix+1]  == c);
            s = !(up && dn && lf && rt);
        }
        d_surf[(pair*2+0)*HW + pix] = s ? 1 : 0;
    }
    {
        const int* T = target + (size_t)b*HW;
        bool fg = (T[pix] == c);
        bool s = false;
        if (fg) {
            bool up = (i > 0)     && (T[pix-WW] == c);
            bool dn = (i < HH-1)  && (T[pix+WW] == c);
            bool lf = (j > 0)     && (T[pix-1]  == c);
            bool rt = (j < WW-1)  && (T[pix+1]  == c);
            s = !(up && dn && lf && rt);
        }
        d_surf[(pair*2+1)*HW + pix] = s ? 1 : 0;
    }
}

// ---------------------------------------------------------------- compact: per-(mask,row) list of surface columns
// One warp per row. Order within the list is irrelevant (histogram scatter).
__global__ void compact_kernel() {
    int warps_per_blk = blockDim.x >> 5;
    int gw = blockIdx.x*warps_per_blk + (threadIdx.x >> 5);  // row id in [0, NM*HH)
    int lane = threadIdx.x & 31;
    if (gw >= NM*HH) return;
    int m = gw / HH;
    int i = gw - m*HH;
    const unsigned char* s = d_surf + m*HW + i*WW;
    unsigned char* out = d_cols + m*HW + i*WW;
    int base = 0;
    #pragma unroll
    for (int c = 0; c < 6; c++) {
        int jj = c*32 + lane;
        bool on = (s[jj] != 0);
        unsigned msk = __ballot_sync(0xffffffffu, on);
        if (on) {
            int pos = base + __popc(msk & ((1u << lane) - 1u));
            out[pos] = (unsigned char)jj;
        }
        base += __popc(msk);
    }
    if (lane == 0) d_cnt[m*HH + i] = (short)base;
}

// ---------------------------------------------------------------- pass 1: per-column squared distance to nearest surface row
// Forward: downward count into smem (uint8; 0 <=> surface voxel, so surf bit is recoverable).
// Backward: pure smem/register, write d^2 as u16 (65535 = no surface in column).
__global__ void colpass_kernel() {
    int m = blockIdx.x;      // 48 masks
    int j = threadIdx.x;     // 192 columns
    __shared__ unsigned char dtmp[HW];
    const unsigned char* s = d_surf + m*HW;
    unsigned short* g = d_g16 + m*HW;
    int cnt = 255;
    #pragma unroll 8
    for (int i = 0; i < HH; i++) {
        unsigned char sv = s[i*WW + j];
        cnt = sv ? 0 : min(cnt + 1, 255);
        dtmp[i*WW + j] = (unsigned char)cnt;
    }
    cnt = 255;
    #pragma unroll 8
    for (int i = HH-1; i >= 0; i--) {
        int du = (int)dtmp[i*WW + j];
        cnt = (du == 0) ? 0 : min(cnt + 1, 255);
        int d = min(cnt, du);
        g[i*WW + j] = (d >= HH) ? (unsigned short)65535 : (unsigned short)(d*d);
    }
}

// ---------------------------------------------------------------- pass 2: min-plus over columns at sampled voxels only
// f(i,j) = min_jp fma((j-jp),(j-jp), g[i,jp]) — exact integers (< 2^24) or ~1e9.
// Samples for mask m live on the opposite surface (m^1).
__global__ void rowpass_kernel() {
    int m = blockIdx.x / HH;
    int i = blockIdx.x - m*HH;
    int cnt = (int)d_cnt[(m ^ 1)*HH + i];
    if (cnt == 0) return;                      // uniform across block
    __shared__ float gs[WW];
    for (int k = threadIdx.x; k < WW; k += blockDim.x) {
        unsigned short v = d_g16[m*HW + i*WW + k];
        gs[k] = (v == 65535) ? 1e9f : (float)v;
    }
    __syncthreads();
    const unsigned char* cols = d_cols + (m ^ 1)*HW + i*WW;
    for (int t = threadIdx.x; t < cnt; t += blockDim.x) {
        float jj = (float)cols[t];
        float v = 3.0e9f;
        #pragma unroll 8
        for (int jp = 0; jp < WW; jp++) {
            float dd = jj - (float)jp;
            v = fminf(v, fmaf(dd, dd, gs[jp]));
        }
        int key = (v > 73000.0f) ? SENT_KEY : (int)v;   // v is an exact integer or ~1e9
        atomicAdd(&d_coarse[m*NCOARSE + (key >> 8)], 1);
        atomicAdd(&d_hist[m*NBINS + key], 1);
    }
}

// ---------------------------------------------------------------- per-mask selection: p95 rank = ceil(0.95f*n), p100 rank = n
__global__ void select_kernel() {
    int m = blockIdx.x;
    __shared__ int cs[NCOARSE];
    __shared__ int fs[2][256];
    __shared__ int cbsel[2];
    __shared__ int rrem[2];
    __shared__ int nsh;
    int t = threadIdx.x;
    if (t < NCOARSE) cs[t] = d_coarse[m*NCOARSE + t];
    __syncthreads();
    if (t == 0) {
        int n = 0;
        for (int k = 0; k < NCOARSE; k++) n += cs[k];
        nsh = n;
        if (n > 0) {
            int r95 = (int)ceilf(0.95f * (float)n);   // matches jnp: f32 0.95 * f32 n, ceil
            if (r95 < 1) r95 = 1;
            if (r95 > n) r95 = n;
            int ranks[2] = { r95, n };
            for (int q = 0; q < 2; q++) {
                int r = ranks[q];
                int cum = 0, cb = NCOARSE - 1;
                for (int k = 0; k < NCOARSE; k++) {
                    if (cum + cs[k] >= r) { cb = k; break; }
                    cum += cs[k];
                }
                cbsel[q] = cb;
                rrem[q]  = r - cum;
            }
        }
    }
    __syncthreads();
    if (nsh == 0) {
        if (t < 2) d_res[m*2 + t] = INFINITY;
        return;
    }
    for (int q = 0; q < 2; q++)
        if (t < 256) fs[q][t] = d_hist[m*NBINS + cbsel[q]*256 + t];
    __syncthreads();
    if (t == 0) {
        for (int q = 0; q < 2; q++) {
            int cum = 0;
            int key = cbsel[q]*256;
            for (int k = 0; k < 256; k++) {
                cum += fs[q][k];
                if (cum >= rrem[q]) { key += k; break; }
            }
            float val = (key == SENT_KEY) ? sqrtf(1e9f) : sqrtf((float)key);
            d_res[m*2 + q] = val;  // q=0: p95, q=1: p100
        }
    }
}

// ---------------------------------------------------------------- combine: max over directions, mean over 24 pairs
__global__ void final_kernel(float* __restrict__ out) {
    if (threadIdx.x == 0) {
        float s100 = 0.0f, s95 = 0.0f;
        #pragma unroll
        for (int p = 0; p < NP; p++) {
            s95  += fmaxf(d_res[(2*p)*2 + 0], d_res[(2*p+1)*2 + 0]);
            s100 += fmaxf(d_res[(2*p)*2 + 1], d_res[(2*p+1)*2 + 1]);
        }
        out[0] = s100 / (float)NP;
        out[1] = s95  / (float)NP;
    }
}

extern "C" void kernel_launch(void* const* d_in, const int* in_sizes, int n_in,
                              void* d_out, int out_size) {
    const float* logits = (const float*)d_in[0];
    const int*   target = (const int*)d_in[1];
    float* out = (float*)d_out;

    clear_kernel  <<<2048, 256>>>();
    argmax_kernel <<<(BB*HW + 255)/256, 256>>>(logits);
    surface_kernel<<<(NP*HW + 255)/256, 256>>>(target);
    compact_kernel<<<(NM*HH + 3)/4, 128>>>();
    colpass_kernel<<<NM, WW>>>();
    rowpass_kernel<<<NM*HH, 96>>>();
    select_kernel <<<NM, NCOARSE>>>();
    final_kernel  <<<1, 32>>>(out);
}